// round 3
// baseline (speedup 1.0000x reference)
#include <cuda_runtime.h>
#include <cstdint>

#define N_FFT 8192
#define NT    512
#define D_CH  512
#define SEQ   4096
#define NBATCH 4

// Padded smem index: +1 float2 every 16
#define PADI(i) ((i) + ((i) >> 4))
#define BUFSZ (N_FFT + (N_FFT >> 4))   // 8704 float2 = 69632 B (single buffer!)

__device__ float2 g_tw[N_FFT];                          // exp(-2*pi*i*k/N)
__device__ float2 g_tfft[(size_t)D_CH * N_FFT];         // t spectra (33.5 MB)
__device__ float  g_xT[(size_t)NBATCH * D_CH * SEQ];
__device__ float  g_tT[(size_t)D_CH * 2 * SEQ];
__device__ float  g_oT[(size_t)NBATCH * D_CH * SEQ];

__device__ __forceinline__ float2 cadd(float2 a, float2 b) { return make_float2(a.x + b.x, a.y + b.y); }
__device__ __forceinline__ float2 csub(float2 a, float2 b) { return make_float2(a.x - b.x, a.y - b.y); }
__device__ __forceinline__ float2 cmul(float2 a, float2 b) {
    return make_float2(a.x * b.x - a.y * b.y, a.x * b.y + a.y * b.x);
}
// forward: *(-i); inverse: *(+i)
template <bool INV>
__device__ __forceinline__ float2 mulJ(float2 z) {
    return INV ? make_float2(-z.y, z.x) : make_float2(z.y, -z.x);
}
// multiply by (re, im) forward, (re, -im) inverse
template <bool INV>
__device__ __forceinline__ float2 twc(float2 z, float re, float im) {
    float2 w = make_float2(re, INV ? -im : im);
    return cmul(z, w);
}

// 4-point DFT in place: (a0,a1,a2,a3) -> (y0,y1,y2,y3)
template <bool INV>
__device__ __forceinline__ void dft4(float2& a0, float2& a1, float2& a2, float2& a3) {
    float2 t0 = cadd(a0, a2), t1 = csub(a0, a2);
    float2 t2 = cadd(a1, a3), t3 = mulJ<INV>(csub(a1, a3));
    a0 = cadd(t0, t2);
    a1 = cadd(t1, t3);
    a2 = csub(t0, t2);
    a3 = csub(t1, t3);
}

// 16-point DFT. Output y[r] ends up at a[SW16[r]] (base-4 digit swap).
__device__ __constant__ int SW16[16] = {0,4,8,12, 1,5,9,13, 2,6,10,14, 3,7,11,15};

template <bool INV>
__device__ __forceinline__ void dft16(float2 a[16]) {
    const float C1 = 0.92387953251128675613f;  // cos(pi/8)
    const float S1 = 0.38268343236508977173f;  // sin(pi/8)
    const float H  = 0.70710678118654752440f;  // sqrt(2)/2
    // stage 1: DFT4 over jo for each ji; b_{ji}[ro] = a[ji + 4*ro]
#pragma unroll
    for (int ji = 0; ji < 4; ji++) dft4<INV>(a[ji], a[ji + 4], a[ji + 8], a[ji + 12]);
    // stage 2: twiddle W16^{ji*ro}
    a[5]  = twc<INV>(a[5],  C1, -S1);   // (1,1)
    a[9]  = twc<INV>(a[9],   H,  -H);   // (1,2)
    a[13] = twc<INV>(a[13], S1, -C1);   // (1,3)
    a[6]  = twc<INV>(a[6],   H,  -H);   // (2,1)
    a[10] = mulJ<INV>(a[10]);           // (2,2) = W16^4
    a[14] = twc<INV>(a[14], -H,  -H);   // (2,3)
    a[7]  = twc<INV>(a[7],  S1, -C1);   // (3,1)
    a[11] = twc<INV>(a[11], -H,  -H);   // (3,2)
    a[15] = twc<INV>(a[15], -C1, S1);   // (3,3) = W16^9
    // stage 3: DFT4 over ji for each ro
#pragma unroll
    for (int ro = 0; ro < 4; ro++) dft4<INV>(a[4 * ro], a[4 * ro + 1], a[4 * ro + 2], a[4 * ro + 3]);
}

// In-place radix-16 Stockham pass. Reads are always X[tid + 512*r].
// FIRST: take input from ain (gmem-loaded regs) instead of smem, skip pre-write sync.
template <bool INV, bool FIRST>
__device__ __forceinline__ void pass16(float2* __restrict__ X, const float2* ain, int sLog, int tid) {
    float2 a[16];
    if (FIRST) {
#pragma unroll
        for (int r = 0; r < 16; r++) a[r] = ain[r];
    } else {
#pragma unroll
        for (int r = 0; r < 16; r++) a[r] = X[PADI(tid + 512 * r)];
    }
    dft16<INV>(a);
    const int s = 1 << sLog;
    const int q = tid & (s - 1);
    const int p = tid >> sLog;
    const int tb = p << sLog;  // p*s
    float2 w[16];
#pragma unroll
    for (int r = 1; r < 16; r++) {
        w[r] = g_tw[r * tb];
        if (INV) w[r].y = -w[r].y;
    }
    if (!FIRST) __syncthreads();   // all reads complete before in-place writes
#pragma unroll
    for (int r = 0; r < 16; r++) {
        float2 v = a[SW16[r]];
        if (r > 0) v = cmul(v, w[r]);
        X[PADI(q + (((p << 4) + r) << sLog))] = v;
    }
    __syncthreads();
}

// ---------------------------------------------------------------------------
__global__ void ker_tw() {
    int k = blockIdx.x * blockDim.x + threadIdx.x;
    if (k < N_FFT) {
        float s, c;
        sincospif(-2.0f * (float)k / (float)N_FFT, &s, &c);
        g_tw[k] = make_float2(c, s);
    }
}

// Tiled transpose: in[b][r][c] -> out[b][c][r]
__global__ void __launch_bounds__(256) ker_T(const float* __restrict__ in, float* __restrict__ out,
                                             int R, int C) {
    __shared__ float tile[32][33];
    const size_t boff = (size_t)blockIdx.z * R * C;
    const float* I = in + boff;
    float* O = out + boff;
    const int c0 = blockIdx.x * 32, r0 = blockIdx.y * 32;
    const int cx = c0 + threadIdx.x;
#pragma unroll
    for (int i = threadIdx.y; i < 32; i += 8)
        tile[i][threadIdx.x] = I[(size_t)(r0 + i) * C + cx];
    __syncthreads();
    const int rx = r0 + threadIdx.x;
#pragma unroll
    for (int i = threadIdx.y; i < 32; i += 8)
        O[(size_t)(c0 + i) * R + rx] = tile[threadIdx.x][i];
}

// t spectrum: block handles channels (2c, 2c+1) as real+imag of one FFT.
__global__ void __launch_bounds__(NT, 2) ker_tfft() {
    extern __shared__ float2 sm[];
    float2* X = sm;
    const int c0 = blockIdx.x;  // 0..255
    const int tid = threadIdx.x;
    const float* t0 = g_tT + (size_t)(2 * c0) * N_FFT;
    const float* t1 = t0 + N_FFT;

    float2 a[16];
#pragma unroll
    for (int r = 0; r < 16; r++)
        a[r] = make_float2(t0[tid + 512 * r], t1[tid + 512 * r]);

    pass16<false, true>(X, a, 0, tid);
    pass16<false, false>(X, nullptr, 4, tid);
    pass16<false, false>(X, nullptr, 8, tid);
    // final radix-2 (s=4096), in place
    {
        float2 u[8], v[8];
#pragma unroll
        for (int i = 0; i < 8; i++) {
            int q = tid + 512 * i;
            u[i] = X[PADI(q)];
            v[i] = X[PADI(q + N_FFT / 2)];
        }
        __syncthreads();
#pragma unroll
        for (int i = 0; i < 8; i++) {
            int q = tid + 512 * i;
            X[PADI(q)] = cadd(u[i], v[i]);
            X[PADI(q + N_FFT / 2)] = csub(u[i], v[i]);
        }
        __syncthreads();
    }
    // Hermitian unpack: Z = T0 + i*T1
    float2* out0 = g_tfft + (size_t)(2 * c0) * N_FFT;
    float2* out1 = g_tfft + (size_t)(2 * c0 + 1) * N_FFT;
    for (int k = tid; k < N_FFT; k += NT) {
        float2 Zk = X[PADI(k)];
        float2 Zn = X[PADI((N_FFT - k) & (N_FFT - 1))];
        out0[k] = make_float2(0.5f * (Zk.x + Zn.x), 0.5f * (Zk.y - Zn.y));
        out1[k] = make_float2(0.5f * (Zk.y + Zn.y), -0.5f * (Zk.x - Zn.x));
    }
}

// Convolution: one block per (batch-pair, channel). z = x[b0] + i*x[b1].
__global__ void __launch_bounds__(NT, 2) ker_conv() {
    extern __shared__ float2 sm[];
    float2* X = sm;
    const int blk = blockIdx.x;       // 0..1023
    const int d = blk & (D_CH - 1);
    const int pr = blk >> 9;
    const int tid = threadIdx.x;
    const float* x0 = g_xT + ((size_t)(2 * pr) * D_CH + d) * SEQ;
    const float* x1 = x0 + (size_t)D_CH * SEQ;

    // load (zero-pad r>=8 since SEQ = 8*512) and run forward FFT stage 1 from regs
    float2 a[16];
#pragma unroll
    for (int r = 0; r < 8; r++)
        a[r] = make_float2(x0[tid + 512 * r], x1[tid + 512 * r]);
#pragma unroll
    for (int r = 8; r < 16; r++) a[r] = make_float2(0.0f, 0.0f);

    pass16<false, true>(X, a, 0, tid);
    pass16<false, false>(X, nullptr, 4, tid);
    pass16<false, false>(X, nullptr, 8, tid);

    // fused: final radix-2 of forward FFT + pointwise multiply + 1/N scale
    const float2* tf = g_tfft + (size_t)d * N_FFT;
    const float inv = 1.0f / (float)N_FFT;
    {
        float2 u[8], v[8];
#pragma unroll
        for (int i = 0; i < 8; i++) {
            int q = tid + 512 * i;
            u[i] = X[PADI(q)];
            v[i] = X[PADI(q + N_FFT / 2)];
        }
#pragma unroll
        for (int i = 0; i < 8; i++) {
            int q = tid + 512 * i;
            float2 s = cadd(u[i], v[i]);
            float2 dd = csub(u[i], v[i]);
            float2 w0 = tf[q];
            float2 w1 = tf[q + N_FFT / 2];
            s = cmul(s, w0);
            dd = cmul(dd, w1);
            u[i] = make_float2(s.x * inv, s.y * inv);
            v[i] = make_float2(dd.x * inv, dd.y * inv);
        }
        __syncthreads();
#pragma unroll
        for (int i = 0; i < 8; i++) {
            int q = tid + 512 * i;
            X[PADI(q)] = u[i];
            X[PADI(q + N_FFT / 2)] = v[i];
        }
        __syncthreads();
    }

    // inverse FFT
    pass16<true, false>(X, nullptr, 0, tid);
    pass16<true, false>(X, nullptr, 4, tid);
    pass16<true, false>(X, nullptr, 8, tid);

    // final radix-2 of inverse: only the first half (q < 4096) is needed -> sum only,
    // write straight to gmem (deinterleave batch pair).
    float* o0 = g_oT + ((size_t)(2 * pr) * D_CH + d) * SEQ;
    float* o1 = o0 + (size_t)D_CH * SEQ;
#pragma unroll
    for (int i = 0; i < 8; i++) {
        int q = tid + 512 * i;
        float2 s = cadd(X[PADI(q)], X[PADI(q + N_FFT / 2)]);
        o0[q] = s.x;
        o1[q] = s.y;
    }
}

extern "C" void kernel_launch(void* const* d_in, const int* in_sizes, int n_in,
                              void* d_out, int out_size) {
    const float* x = (const float*)d_in[0];
    const float* t = (const float*)d_in[1];
    if (n_in >= 2 && in_sizes[0] < in_sizes[1]) {
        const float* tmp = x; x = t; t = tmp;
    }
    float* o = (float*)d_out;

    float* xT;  cudaGetSymbolAddress((void**)&xT, g_xT);
    float* tT;  cudaGetSymbolAddress((void**)&tT, g_tT);
    float* oT;  cudaGetSymbolAddress((void**)&oT, g_oT);

    const size_t smem = (size_t)BUFSZ * sizeof(float2);  // 69632 B -> 2 blocks/SM
    cudaFuncSetAttribute(ker_tfft, cudaFuncAttributeMaxDynamicSharedMemorySize, (int)smem);
    cudaFuncSetAttribute(ker_conv, cudaFuncAttributeMaxDynamicSharedMemorySize, (int)smem);

    ker_tw<<<(N_FFT + 255) / 256, 256>>>();

    {
        dim3 blk(32, 8);
        dim3 gx(D_CH / 32, SEQ / 32, NBATCH);
        ker_T<<<gx, blk>>>(x, xT, SEQ, D_CH);
        dim3 gt(D_CH / 32, (2 * SEQ) / 32, 1);
        ker_T<<<gt, blk>>>(t, tT, 2 * SEQ, D_CH);
    }

    ker_tfft<<<D_CH / 2, NT, smem>>>();
    ker_conv<<<2 * D_CH, NT, smem>>>();

    {
        dim3 blk(32, 8);
        dim3 go(SEQ / 32, D_CH / 32, NBATCH);
        ker_T<<<go, blk>>>(oT, o, D_CH, SEQ);
    }
}

// round 4
// speedup vs baseline: 1.2893x; 1.2893x over previous
#include <cuda_runtime.h>
#include <cstdint>

#define N_FFT 8192
#define NT    512
#define D_CH  512
#define SEQ   4096
#define NBATCH 4

// Padded smem index: +1 float2 every 16
#define PADI(i) ((i) + ((i) >> 4))
#define BUFSZ (N_FFT + (N_FFT >> 4))   // 8704 float2 = 69632 B (single buffer)

__device__ float2 g_tw[N_FFT];                          // exp(-2*pi*i*k/N)
__device__ float2 g_tfft[(size_t)D_CH * N_FFT];         // t spectra (33.5 MB)
__device__ float  g_xT[(size_t)NBATCH * D_CH * SEQ];
__device__ float  g_tT[(size_t)D_CH * 2 * SEQ];
__device__ float  g_oT[(size_t)NBATCH * D_CH * SEQ];

__device__ __forceinline__ float2 cadd(float2 a, float2 b) { return make_float2(a.x + b.x, a.y + b.y); }
__device__ __forceinline__ float2 csub(float2 a, float2 b) { return make_float2(a.x - b.x, a.y - b.y); }
__device__ __forceinline__ float2 cmul(float2 a, float2 b) {
    return make_float2(a.x * b.x - a.y * b.y, a.x * b.y + a.y * b.x);
}
template <bool INV>
__device__ __forceinline__ float2 mulJ(float2 z) {
    return INV ? make_float2(-z.y, z.x) : make_float2(z.y, -z.x);
}
template <bool INV>
__device__ __forceinline__ float2 twc(float2 z, float re, float im) {
    float2 w = make_float2(re, INV ? -im : im);
    return cmul(z, w);
}

template <bool INV>
__device__ __forceinline__ void dft4(float2& a0, float2& a1, float2& a2, float2& a3) {
    float2 t0 = cadd(a0, a2), t1 = csub(a0, a2);
    float2 t2 = cadd(a1, a3), t3 = mulJ<INV>(csub(a1, a3));
    a0 = cadd(t0, t2);
    a1 = cadd(t1, t3);
    a2 = csub(t0, t2);
    a3 = csub(t1, t3);
}

// 16-point DFT; output y[r] lands at a[SW16[r]] (base-4 digit swap)
__device__ __constant__ int SW16[16] = {0,4,8,12, 1,5,9,13, 2,6,10,14, 3,7,11,15};

template <bool INV>
__device__ __forceinline__ void dft16(float2 a[16]) {
    const float C1 = 0.92387953251128675613f;
    const float S1 = 0.38268343236508977173f;
    const float H  = 0.70710678118654752440f;
#pragma unroll
    for (int ji = 0; ji < 4; ji++) dft4<INV>(a[ji], a[ji + 4], a[ji + 8], a[ji + 12]);
    a[5]  = twc<INV>(a[5],  C1, -S1);
    a[9]  = twc<INV>(a[9],   H,  -H);
    a[13] = twc<INV>(a[13], S1, -C1);
    a[6]  = twc<INV>(a[6],   H,  -H);
    a[10] = mulJ<INV>(a[10]);
    a[14] = twc<INV>(a[14], -H,  -H);
    a[7]  = twc<INV>(a[7],  S1, -C1);
    a[11] = twc<INV>(a[11], -H,  -H);
    a[15] = twc<INV>(a[15], -C1, S1);
#pragma unroll
    for (int ro = 0; ro < 4; ro++) dft4<INV>(a[4 * ro], a[4 * ro + 1], a[4 * ro + 2], a[4 * ro + 3]);
}

// In-place radix-16 Stockham pass. Reads at X[tid + 512*r]; incremental twiddles
// after the sync keep live registers ~38 floats (no spill at 64-reg cap).
template <bool INV, bool FIRST>
__device__ __forceinline__ void pass16(float2* __restrict__ X, const float2* ain, int sLog, int tid) {
    float2 a[16];
    if (FIRST) {
#pragma unroll
        for (int r = 0; r < 16; r++) a[r] = ain[r];
    } else {
#pragma unroll
        for (int r = 0; r < 16; r++) a[r] = X[PADI(tid + 512 * r)];
    }
    dft16<INV>(a);
    const int s = 1 << sLog;
    const int q = tid & (s - 1);
    const int p = tid >> sLog;
    const int tb = p << sLog;          // p*s
    if (!FIRST) __syncthreads();       // all reads complete before in-place writes
    float2 w1 = g_tw[tb];
    if (INV) w1.y = -w1.y;
    const int ob = q + (p << (sLog + 4));
    X[PADI(ob)] = a[SW16[0]];
    float2 w = w1;
#pragma unroll
    for (int r = 1; r < 16; r++) {
        X[PADI(ob + (r << sLog))] = cmul(a[SW16[r]], w);
        w = cmul(w, w1);
    }
    __syncthreads();
}

// ---------------------------------------------------------------------------
__global__ void ker_tw() {
    int k = blockIdx.x * blockDim.x + threadIdx.x;
    if (k < N_FFT) {
        float s, c;
        sincospif(-2.0f * (float)k / (float)N_FFT, &s, &c);
        g_tw[k] = make_float2(c, s);
    }
}

__global__ void __launch_bounds__(256) ker_T(const float* __restrict__ in, float* __restrict__ out,
                                             int R, int C) {
    __shared__ float tile[32][33];
    const size_t boff = (size_t)blockIdx.z * R * C;
    const float* I = in + boff;
    float* O = out + boff;
    const int c0 = blockIdx.x * 32, r0 = blockIdx.y * 32;
    const int cx = c0 + threadIdx.x;
#pragma unroll
    for (int i = threadIdx.y; i < 32; i += 8)
        tile[i][threadIdx.x] = I[(size_t)(r0 + i) * C + cx];
    __syncthreads();
    const int rx = r0 + threadIdx.x;
#pragma unroll
    for (int i = threadIdx.y; i < 32; i += 8)
        O[(size_t)(c0 + i) * R + rx] = tile[threadIdx.x][i];
}

// t spectrum: block handles channels (2c, 2c+1) as real+imag of one FFT.
__global__ void __launch_bounds__(NT, 2) ker_tfft() {
    extern __shared__ float2 sm[];
    float2* X = sm;
    const int c0 = blockIdx.x;
    const int tid = threadIdx.x;
    const float* t0 = g_tT + (size_t)(2 * c0) * N_FFT;
    const float* t1 = t0 + N_FFT;

    float2 a[16];
#pragma unroll
    for (int r = 0; r < 16; r++)
        a[r] = make_float2(t0[tid + 512 * r], t1[tid + 512 * r]);

    pass16<false, true>(X, a, 0, tid);
    pass16<false, false>(X, nullptr, 4, tid);
    pass16<false, false>(X, nullptr, 8, tid);
    // final radix-2 (s=4096): per-thread-owned slot pairs -> stream, no internal sync
#pragma unroll
    for (int i = 0; i < 8; i++) {
        int q = tid + 512 * i;
        float2 u = X[PADI(q)];
        float2 v = X[PADI(q + N_FFT / 2)];
        X[PADI(q)] = cadd(u, v);
        X[PADI(q + N_FFT / 2)] = csub(u, v);
    }
    __syncthreads();
    // Hermitian unpack: Z = T0 + i*T1
    float2* out0 = g_tfft + (size_t)(2 * c0) * N_FFT;
    float2* out1 = g_tfft + (size_t)(2 * c0 + 1) * N_FFT;
    for (int k = tid; k < N_FFT; k += NT) {
        float2 Zk = X[PADI(k)];
        float2 Zn = X[PADI((N_FFT - k) & (N_FFT - 1))];
        out0[k] = make_float2(0.5f * (Zk.x + Zn.x), 0.5f * (Zk.y - Zn.y));
        out1[k] = make_float2(0.5f * (Zk.y + Zn.y), -0.5f * (Zk.x - Zn.x));
    }
}

// Convolution: one block per (batch-pair, channel). z = x[b0] + i*x[b1].
__global__ void __launch_bounds__(NT, 2) ker_conv() {
    extern __shared__ float2 sm[];
    float2* X = sm;
    const int blk = blockIdx.x;
    const int d = blk & (D_CH - 1);
    const int pr = blk >> 9;
    const int tid = threadIdx.x;
    const float* x0 = g_xT + ((size_t)(2 * pr) * D_CH + d) * SEQ;
    const float* x1 = x0 + (size_t)D_CH * SEQ;

    float2 a[16];
#pragma unroll
    for (int r = 0; r < 8; r++)
        a[r] = make_float2(x0[tid + 512 * r], x1[tid + 512 * r]);
#pragma unroll
    for (int r = 8; r < 16; r++) a[r] = make_float2(0.0f, 0.0f);

    pass16<false, true>(X, a, 0, tid);
    pass16<false, false>(X, nullptr, 4, tid);
    pass16<false, false>(X, nullptr, 8, tid);

    // fused: final radix-2 of forward + pointwise multiply + 1/N scale.
    // Per-thread-owned slot pairs -> stream, no internal sync, minimal live regs.
    const float2* tf = g_tfft + (size_t)d * N_FFT;
    const float inv = 1.0f / (float)N_FFT;
#pragma unroll
    for (int i = 0; i < 8; i++) {
        int q = tid + 512 * i;
        float2 u = X[PADI(q)];
        float2 v = X[PADI(q + N_FFT / 2)];
        float2 s = cmul(cadd(u, v), tf[q]);
        float2 dd = cmul(csub(u, v), tf[q + N_FFT / 2]);
        X[PADI(q)] = make_float2(s.x * inv, s.y * inv);
        X[PADI(q + N_FFT / 2)] = make_float2(dd.x * inv, dd.y * inv);
    }
    __syncthreads();

    pass16<true, false>(X, nullptr, 0, tid);
    pass16<true, false>(X, nullptr, 4, tid);
    pass16<true, false>(X, nullptr, 8, tid);

    // final radix-2 of inverse: only first half needed -> sum only, straight to gmem
    float* o0 = g_oT + ((size_t)(2 * pr) * D_CH + d) * SEQ;
    float* o1 = o0 + (size_t)D_CH * SEQ;
#pragma unroll
    for (int i = 0; i < 8; i++) {
        int q = tid + 512 * i;
        float2 s = cadd(X[PADI(q)], X[PADI(q + N_FFT / 2)]);
        o0[q] = s.x;
        o1[q] = s.y;
    }
}

extern "C" void kernel_launch(void* const* d_in, const int* in_sizes, int n_in,
                              void* d_out, int out_size) {
    const float* x = (const float*)d_in[0];
    const float* t = (const float*)d_in[1];
    if (n_in >= 2 && in_sizes[0] < in_sizes[1]) {
        const float* tmp = x; x = t; t = tmp;
    }
    float* o = (float*)d_out;

    float* xT;  cudaGetSymbolAddress((void**)&xT, g_xT);
    float* tT;  cudaGetSymbolAddress((void**)&tT, g_tT);
    float* oT;  cudaGetSymbolAddress((void**)&oT, g_oT);

    const size_t smem = (size_t)BUFSZ * sizeof(float2);  // 69632 B -> 2 blocks/SM
    cudaFuncSetAttribute(ker_tfft, cudaFuncAttributeMaxDynamicSharedMemorySize, (int)smem);
    cudaFuncSetAttribute(ker_conv, cudaFuncAttributeMaxDynamicSharedMemorySize, (int)smem);

    ker_tw<<<(N_FFT + 255) / 256, 256>>>();

    {
        dim3 blk(32, 8);
        dim3 gx(D_CH / 32, SEQ / 32, NBATCH);
        ker_T<<<gx, blk>>>(x, xT, SEQ, D_CH);
        dim3 gt(D_CH / 32, (2 * SEQ) / 32, 1);
        ker_T<<<gt, blk>>>(t, tT, 2 * SEQ, D_CH);
    }

    ker_tfft<<<D_CH / 2, NT, smem>>>();
    ker_conv<<<2 * D_CH, NT, smem>>>();

    {
        dim3 blk(32, 8);
        dim3 go(SEQ / 32, D_CH / 32, NBATCH);
        ker_T<<<go, blk>>>(oT, o, D_CH, SEQ);
    }
}

// round 6
// speedup vs baseline: 1.7261x; 1.3387x over previous
#include <cuda_runtime.h>
#include <cstdint>

#define N_FFT 8192
#define NT    512
#define D_CH  512
#define SEQ   4096
#define NBATCH 4

// Padded smem index: +1 float2 every 16
#define PADI(i) ((i) + ((i) >> 4))
#define BUFSZ (N_FFT + (N_FFT >> 4))   // 8704 float2 = 69632 B

__device__ float2 g_tw[N_FFT];                          // exp(-2*pi*i*k/N)
__device__ float2 g_tfft[(size_t)D_CH * N_FFT];         // t spectra (33.5 MB)
__device__ float  g_xT[(size_t)NBATCH * D_CH * SEQ];
__device__ float  g_tT[(size_t)D_CH * 2 * SEQ];
__device__ float  g_oT[(size_t)NBATCH * D_CH * SEQ];

__device__ __forceinline__ float2 cadd(float2 a, float2 b) { return make_float2(a.x + b.x, a.y + b.y); }
__device__ __forceinline__ float2 csub(float2 a, float2 b) { return make_float2(a.x - b.x, a.y - b.y); }
__device__ __forceinline__ float2 cmul(float2 a, float2 b) {
    return make_float2(a.x * b.x - a.y * b.y, a.x * b.y + a.y * b.x);
}
template <bool INV>
__device__ __forceinline__ float2 mulJ(float2 z) {
    return INV ? make_float2(-z.y, z.x) : make_float2(z.y, -z.x);
}
template <bool INV>
__device__ __forceinline__ float2 twc(float2 z, float re, float im) {
    float2 w = make_float2(re, INV ? -im : im);
    return cmul(z, w);
}

template <bool INV>
__device__ __forceinline__ void dft4(float2& a0, float2& a1, float2& a2, float2& a3) {
    float2 t0 = cadd(a0, a2), t1 = csub(a0, a2);
    float2 t2 = cadd(a1, a3), t3 = mulJ<INV>(csub(a1, a3));
    a0 = cadd(t0, t2);
    a1 = cadd(t1, t3);
    a2 = csub(t0, t2);
    a3 = csub(t1, t3);
}

template <bool INV>
__device__ __forceinline__ void dft16(float2 a[16]) {
    const float C1 = 0.92387953251128675613f;
    const float S1 = 0.38268343236508977173f;
    const float H  = 0.70710678118654752440f;
#pragma unroll
    for (int ji = 0; ji < 4; ji++) dft4<INV>(a[ji], a[ji + 4], a[ji + 8], a[ji + 12]);
    a[5]  = twc<INV>(a[5],  C1, -S1);
    a[9]  = twc<INV>(a[9],   H,  -H);
    a[13] = twc<INV>(a[13], S1, -C1);
    a[6]  = twc<INV>(a[6],   H,  -H);
    a[10] = mulJ<INV>(a[10]);
    a[14] = twc<INV>(a[14], -H,  -H);
    a[7]  = twc<INV>(a[7],  S1, -C1);
    a[11] = twc<INV>(a[11], -H,  -H);
    a[15] = twc<INV>(a[15], -C1, S1);
#pragma unroll
    for (int ro = 0; ro < 4; ro++) dft4<INV>(a[4 * ro], a[4 * ro + 1], a[4 * ro + 2], a[4 * ro + 3]);
}

// Write phase of an in-place radix-16 Stockham pass. Caller syncs around it.
// Output y[r] lands at a[SW16[r]] (base-4 digit swap); local constexpr -> folded.
// Two incremental twiddle chains (from w1 and w8): max serial depth 7.
template <bool INV>
__device__ __forceinline__ void pass16_write(float2* __restrict__ X, const float2 a[16],
                                             int sLog, int tid) {
    constexpr int SW16[16] = {0,4,8,12, 1,5,9,13, 2,6,10,14, 3,7,11,15};
    const int q = tid & ((1 << sLog) - 1);
    const int p = tid >> sLog;
    const int tb = p << sLog;
    float2 w1 = g_tw[tb];
    float2 w8 = g_tw[tb << 3];
    if (INV) { w1.y = -w1.y; w8.y = -w8.y; }
    const int ob = q + (p << (sLog + 4));
    X[PADI(ob)] = a[SW16[0]];
    float2 w = w1;
#pragma unroll
    for (int r = 1; r < 8; r++) {
        X[PADI(ob + (r << sLog))] = cmul(a[SW16[r]], w);
        w = cmul(w, w1);
    }
    X[PADI(ob + (8 << sLog))] = cmul(a[SW16[8]], w8);
    w = cmul(w8, w1);
#pragma unroll
    for (int r = 9; r < 16; r++) {
        X[PADI(ob + (r << sLog))] = cmul(a[SW16[r]], w);
        w = cmul(w, w1);
    }
}

// Generic in-place pass: read -> dft -> sync -> write -> sync
template <bool INV>
__device__ __forceinline__ void pass16(float2* __restrict__ X, int sLog, int tid) {
    float2 a[16];
#pragma unroll
    for (int r = 0; r < 16; r++) a[r] = X[PADI(tid + 512 * r)];
    dft16<INV>(a);
    __syncthreads();
    pass16_write<INV>(X, a, sLog, tid);
    __syncthreads();
}

// ---------------------------------------------------------------------------
__global__ void ker_tw() {
    int k = blockIdx.x * blockDim.x + threadIdx.x;
    if (k < N_FFT) {
        float s, c;
        sincospif(-2.0f * (float)k / (float)N_FFT, &s, &c);
        g_tw[k] = make_float2(c, s);
    }
}

__global__ void __launch_bounds__(256) ker_T(const float* __restrict__ in, float* __restrict__ out,
                                             int R, int C) {
    __shared__ float tile[32][33];
    const size_t boff = (size_t)blockIdx.z * R * C;
    const float* I = in + boff;
    float* O = out + boff;
    const int c0 = blockIdx.x * 32, r0 = blockIdx.y * 32;
    const int cx = c0 + threadIdx.x;
#pragma unroll
    for (int i = threadIdx.y; i < 32; i += 8)
        tile[i][threadIdx.x] = I[(size_t)(r0 + i) * C + cx];
    __syncthreads();
    const int rx = r0 + threadIdx.x;
#pragma unroll
    for (int i = threadIdx.y; i < 32; i += 8)
        O[(size_t)(c0 + i) * R + rx] = tile[threadIdx.x][i];
}

// t spectrum: block handles channels (2c, 2c+1) as real+imag of one FFT.
// Final radix-2 fused into the Hermitian unpack (computed on the fly).
__global__ void __launch_bounds__(NT, 2) ker_tfft() {
    extern __shared__ float2 sm[];
    float2* X = sm;
    const int c0 = blockIdx.x;
    const int tid = threadIdx.x;
    const float* t0 = g_tT + (size_t)(2 * c0) * N_FFT;
    const float* t1 = t0 + N_FFT;

    {
        float2 a[16];
#pragma unroll
        for (int r = 0; r < 16; r++)
            a[r] = make_float2(t0[tid + 512 * r], t1[tid + 512 * r]);
        dft16<false>(a);
        pass16_write<false>(X, a, 0, tid);  // first smem touch: no pre-sync needed
        __syncthreads();
    }
    pass16<false>(X, 4, tid);
    pass16<false>(X, 8, tid);

    // Fused: final radix-2 + Hermitian unpack. Z[k] computed on the fly from Y:
    //   k < 4096: Z[k] = Y[k] + Y[k+4096];  k >= 4096: Z[k] = Y[k-4096] - Y[k]
    float2* out0 = g_tfft + (size_t)(2 * c0) * N_FFT;
    float2* out1 = g_tfft + (size_t)(2 * c0 + 1) * N_FFT;
#pragma unroll
    for (int i = 0; i < 16; i++) {
        int k = tid + 512 * i;
        int kl = k & 4095;
        float2 ua = X[PADI(kl)], ub = X[PADI(kl + 4096)];
        float2 Zk = (k < 4096) ? cadd(ua, ub) : csub(ua, ub);
        int kn = (N_FFT - k) & (N_FFT - 1);
        int knl = kn & 4095;
        float2 va = X[PADI(knl)], vb = X[PADI(knl + 4096)];
        float2 Zn = (kn < 4096) ? cadd(va, vb) : csub(va, vb);
        out0[k] = make_float2(0.5f * (Zk.x + Zn.x), 0.5f * (Zk.y - Zn.y));
        out1[k] = make_float2(0.5f * (Zk.y + Zn.y), -0.5f * (Zk.x - Zn.x));
    }
}

// Convolution: one block per (batch-pair, channel). z = x[b0] + i*x[b1].
__global__ void __launch_bounds__(NT, 2) ker_conv() {
    extern __shared__ float2 sm[];
    float2* X = sm;
    const int blk = blockIdx.x;
    const int d = blk & (D_CH - 1);
    const int pr = blk >> 9;
    const int tid = threadIdx.x;
    const float* x0 = g_xT + ((size_t)(2 * pr) * D_CH + d) * SEQ;
    const float* x1 = x0 + (size_t)D_CH * SEQ;

    // forward pass 0 fused with gmem load (zero-pad r>=8)
    {
        float2 a[16];
#pragma unroll
        for (int r = 0; r < 8; r++)
            a[r] = make_float2(x0[tid + 512 * r], x1[tid + 512 * r]);
#pragma unroll
        for (int r = 8; r < 16; r++) a[r] = make_float2(0.0f, 0.0f);
        dft16<false>(a);
        pass16_write<false>(X, a, 0, tid);
        __syncthreads();
    }
    pass16<false>(X, 4, tid);
    pass16<false>(X, 8, tid);

    // Fused: forward final radix-2 + pointwise multiply (+1/N) + inverse pass 0.
    // Thread's radix-2 pairs (q, q+4096), q = tid+512i, are exactly the 16 inputs
    // tid+512r of its inverse radix-16 butterfly -> do it all in registers.
    {
        const float2* tf = g_tfft + (size_t)d * N_FFT;
        const float inv = 1.0f / (float)N_FFT;
        float2 a[16];
#pragma unroll
        for (int i = 0; i < 8; i++) {
            int q = tid + 512 * i;
            float2 u = X[PADI(q)];
            float2 v = X[PADI(q + 4096)];
            float2 s = cmul(cadd(u, v), tf[q]);
            float2 dd = cmul(csub(u, v), tf[q + 4096]);
            a[i]     = make_float2(s.x * inv, s.y * inv);
            a[i + 8] = make_float2(dd.x * inv, dd.y * inv);
        }
        dft16<true>(a);
        __syncthreads();
        pass16_write<true>(X, a, 0, tid);
        __syncthreads();
    }
    pass16<true>(X, 4, tid);
    pass16<true>(X, 8, tid);

    // final radix-2 of inverse: only first half needed -> sum only, straight to gmem
    float* o0 = g_oT + ((size_t)(2 * pr) * D_CH + d) * SEQ;
    float* o1 = o0 + (size_t)D_CH * SEQ;
#pragma unroll
    for (int i = 0; i < 8; i++) {
        int q = tid + 512 * i;
        float2 s = cadd(X[PADI(q)], X[PADI(q + 4096)]);
        o0[q] = s.x;
        o1[q] = s.y;
    }
}

extern "C" void kernel_launch(void* const* d_in, const int* in_sizes, int n_in,
                              void* d_out, int out_size) {
    const float* x = (const float*)d_in[0];
    const float* t = (const float*)d_in[1];
    if (n_in >= 2 && in_sizes[0] < in_sizes[1]) {
        const float* tmp = x; x = t; t = tmp;
    }
    float* o = (float*)d_out;

    float* xT;  cudaGetSymbolAddress((void**)&xT, g_xT);
    float* tT;  cudaGetSymbolAddress((void**)&tT, g_tT);
    float* oT;  cudaGetSymbolAddress((void**)&oT, g_oT);

    const size_t smem = (size_t)BUFSZ * sizeof(float2);  // 69632 B -> 2 blocks/SM
    cudaFuncSetAttribute(ker_tfft, cudaFuncAttributeMaxDynamicSharedMemorySize, (int)smem);
    cudaFuncSetAttribute(ker_conv, cudaFuncAttributeMaxDynamicSharedMemorySize, (int)smem);

    ker_tw<<<(N_FFT + 255) / 256, 256>>>();

    {
        dim3 blk(32, 8);
        dim3 gx(D_CH / 32, SEQ / 32, NBATCH);
        ker_T<<<gx, blk>>>(x, xT, SEQ, D_CH);
        dim3 gt(D_CH / 32, (2 * SEQ) / 32, 1);
        ker_T<<<gt, blk>>>(t, tT, 2 * SEQ, D_CH);
    }

    ker_tfft<<<D_CH / 2, NT, smem>>>();
    ker_conv<<<2 * D_CH, NT, smem>>>();

    {
        dim3 blk(32, 8);
        dim3 go(SEQ / 32, D_CH / 32, NBATCH);
        ker_T<<<go, blk>>>(oT, o, D_CH, SEQ);
    }
}

// round 7
// speedup vs baseline: 2.0457x; 1.1852x over previous
#include <cuda_runtime.h>
#include <cstdint>

#define N_FFT 8192
#define NT    512
#define D_CH  512
#define SEQ   4096
#define NBATCH 4

// Padded smem index: +1 float2 every 16
#define PADI(i) ((i) + ((i) >> 4))
#define BUFSZ (N_FFT + (N_FFT >> 4))   // 8704 float2 = 69632 B

__device__ float2 g_tw[N_FFT];                          // exp(-2*pi*i*k/N)
__device__ float2 g_tfft[(size_t)D_CH * N_FFT];         // t spectra (33.5 MB)
__device__ float  g_xT[(size_t)NBATCH * D_CH * SEQ];
__device__ float  g_tT[(size_t)D_CH * 2 * SEQ];
__device__ float  g_oT[(size_t)NBATCH * D_CH * SEQ];

__device__ __forceinline__ float2 cadd(float2 a, float2 b) { return make_float2(a.x + b.x, a.y + b.y); }
__device__ __forceinline__ float2 csub(float2 a, float2 b) { return make_float2(a.x - b.x, a.y - b.y); }
__device__ __forceinline__ float2 cmul(float2 a, float2 b) {
    return make_float2(a.x * b.x - a.y * b.y, a.x * b.y + a.y * b.x);
}
template <bool INV>
__device__ __forceinline__ float2 mulJ(float2 z) {
    return INV ? make_float2(-z.y, z.x) : make_float2(z.y, -z.x);
}
template <bool INV>
__device__ __forceinline__ float2 twc(float2 z, float re, float im) {
    float2 w = make_float2(re, INV ? -im : im);
    return cmul(z, w);
}

template <bool INV>
__device__ __forceinline__ void dft4(float2& a0, float2& a1, float2& a2, float2& a3) {
    float2 t0 = cadd(a0, a2), t1 = csub(a0, a2);
    float2 t2 = cadd(a1, a3), t3 = mulJ<INV>(csub(a1, a3));
    a0 = cadd(t0, t2);
    a1 = cadd(t1, t3);
    a2 = csub(t0, t2);
    a3 = csub(t1, t3);
}

template <bool INV>
__device__ __forceinline__ void dft16(float2 a[16]) {
    const float C1 = 0.92387953251128675613f;
    const float S1 = 0.38268343236508977173f;
    const float H  = 0.70710678118654752440f;
#pragma unroll
    for (int ji = 0; ji < 4; ji++) dft4<INV>(a[ji], a[ji + 4], a[ji + 8], a[ji + 12]);
    a[5]  = twc<INV>(a[5],  C1, -S1);
    a[9]  = twc<INV>(a[9],   H,  -H);
    a[13] = twc<INV>(a[13], S1, -C1);
    a[6]  = twc<INV>(a[6],   H,  -H);
    a[10] = mulJ<INV>(a[10]);
    a[14] = twc<INV>(a[14], -H,  -H);
    a[7]  = twc<INV>(a[7],  S1, -C1);
    a[11] = twc<INV>(a[11], -H,  -H);
    a[15] = twc<INV>(a[15], -C1, S1);
#pragma unroll
    for (int ro = 0; ro < 4; ro++) dft4<INV>(a[4 * ro], a[4 * ro + 1], a[4 * ro + 2], a[4 * ro + 3]);
}

// Load the two base twiddles for a pass (independent of smem; call BEFORE the barrier)
template <bool INV>
__device__ __forceinline__ void tw_load(int sLog, int tid, float2& w1, float2& w8) {
    const int tb = (tid >> sLog) << sLog;
    w1 = g_tw[tb];
    w8 = g_tw[tb << 3];
    if (INV) { w1.y = -w1.y; w8.y = -w8.y; }
}

// Write phase of an in-place radix-16 Stockham pass with preloaded twiddles.
// Output y[r] lands at a[SW16[r]] (base-4 digit swap); local constexpr -> folded.
__device__ __forceinline__ void pass16_write(float2* __restrict__ X, const float2 a[16],
                                             int sLog, int tid, float2 w1, float2 w8) {
    constexpr int SW16[16] = {0,4,8,12, 1,5,9,13, 2,6,10,14, 3,7,11,15};
    const int q = tid & ((1 << sLog) - 1);
    const int p = tid >> sLog;
    const int ob = q + (p << (sLog + 4));
    X[PADI(ob)] = a[SW16[0]];
    float2 w = w1;
#pragma unroll
    for (int r = 1; r < 8; r++) {
        X[PADI(ob + (r << sLog))] = cmul(a[SW16[r]], w);
        w = cmul(w, w1);
    }
    X[PADI(ob + (8 << sLog))] = cmul(a[SW16[8]], w8);
    w = cmul(w8, w1);
#pragma unroll
    for (int r = 9; r < 16; r++) {
        X[PADI(ob + (r << sLog))] = cmul(a[SW16[r]], w);
        w = cmul(w, w1);
    }
}

// Generic in-place pass: read -> dft -> (twiddle loads) -> sync -> write -> sync
template <bool INV>
__device__ __forceinline__ void pass16(float2* __restrict__ X, int sLog, int tid) {
    float2 a[16];
#pragma unroll
    for (int r = 0; r < 16; r++) a[r] = X[PADI(tid + 512 * r)];
    dft16<INV>(a);
    float2 w1, w8;
    tw_load<INV>(sLog, tid, w1, w8);   // overlaps the barrier wait
    __syncthreads();
    pass16_write(X, a, sLog, tid, w1, w8);
    __syncthreads();
}

// ---------------------------------------------------------------------------
__global__ void ker_tw() {
    int k = blockIdx.x * blockDim.x + threadIdx.x;
    if (k < N_FFT) {
        float s, c;
        sincospif(-2.0f * (float)k / (float)N_FFT, &s, &c);
        g_tw[k] = make_float2(c, s);
    }
}

// float4 tiled transpose: in[b][r][c] -> out[b][c][r]. 64x64 float tiles, 256 threads.
// R, C multiples of 64. float4 on both gmem sides.
__global__ void __launch_bounds__(256) ker_T4(const float* __restrict__ in, float* __restrict__ out,
                                              int R, int C) {
    __shared__ float tile[64][65];
    const size_t boff = (size_t)blockIdx.z * R * C;
    const float* I = in + boff;
    float* O = out + boff;
    const int c0 = blockIdx.x * 64, r0 = blockIdx.y * 64;
    const int tid = threadIdx.x;
#pragma unroll
    for (int k = 0; k < 4; k++) {
        int idx = k * 256 + tid;           // 0..1023
        int row = idx >> 4;                // 0..63
        int c4  = idx & 15;                // 0..15
        float4 v = *reinterpret_cast<const float4*>(I + (size_t)(r0 + row) * C + c0 + 4 * c4);
        tile[row][4 * c4 + 0] = v.x;
        tile[row][4 * c4 + 1] = v.y;
        tile[row][4 * c4 + 2] = v.z;
        tile[row][4 * c4 + 3] = v.w;
    }
    __syncthreads();
#pragma unroll
    for (int k = 0; k < 4; k++) {
        int idx = k * 256 + tid;
        int c  = idx >> 4;                 // 0..63  (output row = input col)
        int r4 = idx & 15;                 // 0..15  (output col quad)
        float4 v = make_float4(tile[4 * r4 + 0][c], tile[4 * r4 + 1][c],
                               tile[4 * r4 + 2][c], tile[4 * r4 + 3][c]);
        *reinterpret_cast<float4*>(O + (size_t)(c0 + c) * R + r0 + 4 * r4) = v;
    }
}

// t spectrum: block handles channels (2c, 2c+1) as real+imag of one FFT.
// Final radix-2 fused into the Hermitian unpack (computed on the fly).
__global__ void __launch_bounds__(NT, 2) ker_tfft() {
    extern __shared__ float2 sm[];
    float2* X = sm;
    const int c0 = blockIdx.x;
    const int tid = threadIdx.x;
    const float* t0 = g_tT + (size_t)(2 * c0) * N_FFT;
    const float* t1 = t0 + N_FFT;

    {
        float2 a[16];
#pragma unroll
        for (int r = 0; r < 16; r++)
            a[r] = make_float2(t0[tid + 512 * r], t1[tid + 512 * r]);
        dft16<false>(a);
        float2 w1, w8;
        tw_load<false>(0, tid, w1, w8);
        pass16_write(X, a, 0, tid, w1, w8);  // first smem touch: no pre-sync needed
        __syncthreads();
    }
    pass16<false>(X, 4, tid);
    pass16<false>(X, 8, tid);

    // Fused: final radix-2 + Hermitian unpack. Z[k] computed on the fly from Y:
    //   k < 4096: Z[k] = Y[k] + Y[k+4096];  k >= 4096: Z[k] = Y[k-4096] - Y[k]
    float2* out0 = g_tfft + (size_t)(2 * c0) * N_FFT;
    float2* out1 = g_tfft + (size_t)(2 * c0 + 1) * N_FFT;
#pragma unroll
    for (int i = 0; i < 16; i++) {
        int k = tid + 512 * i;
        int kl = k & 4095;
        float2 ua = X[PADI(kl)], ub = X[PADI(kl + 4096)];
        float2 Zk = (k < 4096) ? cadd(ua, ub) : csub(ua, ub);
        int kn = (N_FFT - k) & (N_FFT - 1);
        int knl = kn & 4095;
        float2 va = X[PADI(knl)], vb = X[PADI(knl + 4096)];
        float2 Zn = (kn < 4096) ? cadd(va, vb) : csub(va, vb);
        out0[k] = make_float2(0.5f * (Zk.x + Zn.x), 0.5f * (Zk.y - Zn.y));
        out1[k] = make_float2(0.5f * (Zk.y + Zn.y), -0.5f * (Zk.x - Zn.x));
    }
}

// Convolution: one block per (batch-pair, channel). z = x[b0] + i*x[b1].
__global__ void __launch_bounds__(NT, 2) ker_conv() {
    extern __shared__ float2 sm[];
    float2* X = sm;
    const int blk = blockIdx.x;
    const int d = blk & (D_CH - 1);
    const int pr = blk >> 9;
    const int tid = threadIdx.x;
    const float* x0 = g_xT + ((size_t)(2 * pr) * D_CH + d) * SEQ;
    const float* x1 = x0 + (size_t)D_CH * SEQ;

    // forward pass 0 fused with gmem load (zero-pad r>=8)
    {
        float2 a[16];
#pragma unroll
        for (int r = 0; r < 8; r++)
            a[r] = make_float2(x0[tid + 512 * r], x1[tid + 512 * r]);
#pragma unroll
        for (int r = 8; r < 16; r++) a[r] = make_float2(0.0f, 0.0f);
        dft16<false>(a);
        float2 w1, w8;
        tw_load<false>(0, tid, w1, w8);
        pass16_write(X, a, 0, tid, w1, w8);
        __syncthreads();
    }
    pass16<false>(X, 4, tid);
    pass16<false>(X, 8, tid);

    // Fused: forward final radix-2 + pointwise multiply (+1/N) + inverse pass 0.
    // Thread's radix-2 pairs (q, q+4096), q = tid+512i, are exactly the 16 inputs
    // tid+512r of its inverse radix-16 butterfly -> do it all in registers.
    {
        const float2* tf = g_tfft + (size_t)d * N_FFT;
        const float inv = 1.0f / (float)N_FFT;
        float2 a[16];
#pragma unroll
        for (int i = 0; i < 8; i++) {
            int q = tid + 512 * i;
            float2 u = X[PADI(q)];
            float2 v = X[PADI(q + 4096)];
            float2 s = cmul(cadd(u, v), tf[q]);
            float2 dd = cmul(csub(u, v), tf[q + 4096]);
            a[i]     = make_float2(s.x * inv, s.y * inv);
            a[i + 8] = make_float2(dd.x * inv, dd.y * inv);
        }
        dft16<true>(a);
        float2 w1, w8;
        tw_load<true>(0, tid, w1, w8);
        __syncthreads();
        pass16_write(X, a, 0, tid, w1, w8);
        __syncthreads();
    }
    pass16<true>(X, 4, tid);
    pass16<true>(X, 8, tid);

    // final radix-2 of inverse: only first half needed -> sum only, straight to gmem
    float* o0 = g_oT + ((size_t)(2 * pr) * D_CH + d) * SEQ;
    float* o1 = o0 + (size_t)D_CH * SEQ;
#pragma unroll
    for (int i = 0; i < 8; i++) {
        int q = tid + 512 * i;
        float2 s = cadd(X[PADI(q)], X[PADI(q + 4096)]);
        o0[q] = s.x;
        o1[q] = s.y;
    }
}

extern "C" void kernel_launch(void* const* d_in, const int* in_sizes, int n_in,
                              void* d_out, int out_size) {
    const float* x = (const float*)d_in[0];
    const float* t = (const float*)d_in[1];
    if (n_in >= 2 && in_sizes[0] < in_sizes[1]) {
        const float* tmp = x; x = t; t = tmp;
    }
    float* o = (float*)d_out;

    float* xT;  cudaGetSymbolAddress((void**)&xT, g_xT);
    float* tT;  cudaGetSymbolAddress((void**)&tT, g_tT);
    float* oT;  cudaGetSymbolAddress((void**)&oT, g_oT);

    const size_t smem = (size_t)BUFSZ * sizeof(float2);  // 69632 B -> 2 blocks/SM
    cudaFuncSetAttribute(ker_tfft, cudaFuncAttributeMaxDynamicSharedMemorySize, (int)smem);
    cudaFuncSetAttribute(ker_conv, cudaFuncAttributeMaxDynamicSharedMemorySize, (int)smem);

    ker_tw<<<(N_FFT + 255) / 256, 256>>>();

    {
        dim3 blk(256);
        dim3 gx(D_CH / 64, SEQ / 64, NBATCH);
        ker_T4<<<gx, blk>>>(x, xT, SEQ, D_CH);
        dim3 gt(D_CH / 64, (2 * SEQ) / 64, 1);
        ker_T4<<<gt, blk>>>(t, tT, 2 * SEQ, D_CH);
    }

    ker_tfft<<<D_CH / 2, NT, smem>>>();
    ker_conv<<<2 * D_CH, NT, smem>>>();

    {
        dim3 blk(256);
        dim3 go(SEQ / 64, D_CH / 64, NBATCH);
        ker_T4<<<go, blk>>>(oT, o, D_CH, SEQ);
    }
}